// round 14
// baseline (speedup 1.0000x reference)
#include <cuda_runtime.h>
#include <cuda_fp16.h>
#include <cstdint>
#include <cstddef>

// ---------------------------------------------------------------------------
// Problem constants
// ---------------------------------------------------------------------------
#define OUT_N  11008
#define IN_K   4096
#define NGRPS  (OUT_N * IN_K / 16)   // 2818048
#define M_ROWS 4096                  // 2 * 2048

// Scratch (allocation-free rule: __device__ globals)
__device__ __half g_w[(size_t)OUT_N * IN_K];   // dequantized W, [N, K] K-major
__device__ __half g_x[(size_t)M_ROWS * IN_K];  // fp16 x,        [M, K] K-major

// ---------------------------------------------------------------------------
// Helpers (base sm_103 PTX only: cp.async, ldmatrix, mma.sync)
// ---------------------------------------------------------------------------
__device__ __forceinline__ uint32_t smem_u32(const void* p) {
    uint32_t a;
    asm("{ .reg .u64 t; cvta.to.shared.u64 t, %1; cvt.u32.u64 %0, t; }"
        : "=r"(a) : "l"(p));
    return a;
}

__device__ __forceinline__ void cp_async16(uint32_t dst, const void* src) {
    asm volatile("cp.async.cg.shared.global [%0], [%1], 16;"
                 :: "r"(dst), "l"(src) : "memory");
}
#define CP_COMMIT() asm volatile("cp.async.commit_group;" ::: "memory")
#define CP_WAIT(n)  asm volatile("cp.async.wait_group %0;" :: "n"(n) : "memory")

// memory clobber load-bearing: orders the smem read vs wait/barrier
__device__ __forceinline__ void ldsm_x4(uint32_t* r, uint32_t addr) {
    asm volatile("ldmatrix.sync.aligned.m8n8.x4.shared.b16 {%0,%1,%2,%3}, [%4];"
                 : "=r"(r[0]), "=r"(r[1]), "=r"(r[2]), "=r"(r[3])
                 : "r"(addr) : "memory");
}

__device__ __forceinline__ void mma_16816(float* c, const uint32_t* a,
                                          const uint32_t* b) {
    asm volatile(
        "mma.sync.aligned.m16n8k16.row.col.f32.f16.f16.f32 "
        "{%0,%1,%2,%3}, {%4,%5,%6,%7}, {%8,%9}, {%0,%1,%2,%3};"
        : "+f"(c[0]), "+f"(c[1]), "+f"(c[2]), "+f"(c[3])
        : "r"(a[0]), "r"(a[1]), "r"(a[2]), "r"(a[3]), "r"(b[0]), "r"(b[1]));
}

// SW128 swizzle for 128-byte rows (bijective; same map on write & read)
__device__ __forceinline__ uint32_t swz128(uint32_t off) {
    return off ^ ((off >> 3) & 0x70);
}

// ---------------------------------------------------------------------------
// Kernel 1: dequantize packed 4-bit weights -> fp16 [N, K]
//   weight_norm is FLOAT32 (harness upconverts jax f16 -> f32)  [R12-proven]
// ---------------------------------------------------------------------------
__global__ void dequant_w_kernel(const int* __restrict__ q,
                                 const float* __restrict__ norm) {
    int g = blockIdx.x * blockDim.x + threadIdx.x;
    if (g >= NGRPS) return;
    const int4* qp = (const int4*)q + (size_t)g * 2;
    int4 a = qp[0], b = qp[1];
    float n = norm[g];
    float s = n * (2.0f / 15.0f);
    int v[8] = {a.x, a.y, a.z, a.w, b.x, b.y, b.z, b.w};
    __half2 h[8];
#pragma unroll
    for (int j = 0; j < 8; j++) {
        float lo = (float)(v[j] & 15)        * s - n;   // even position 2j
        float hi = (float)((v[j] >> 4) & 15) * s - n;   // odd position 2j+1
        h[j] = __floats2half2_rn(lo, hi);
    }
    uint4* dst = (uint4*)(g_w + (size_t)g * 16);
    dst[0] = *(uint4*)&h[0];
    dst[1] = *(uint4*)&h[4];
}

// ---------------------------------------------------------------------------
// Kernel 2: x fp32 -> fp16
// ---------------------------------------------------------------------------
__global__ void convert_x_kernel(const float* __restrict__ x, int n4) {
    int i = blockIdx.x * blockDim.x + threadIdx.x;
    if (i >= n4) return;
    float4 v = ((const float4*)x)[i];
    __half2* dst = (__half2*)g_x;
    dst[2 * i]     = __floats2half2_rn(v.x, v.y);
    dst[2 * i + 1] = __floats2half2_rn(v.z, v.w);
}

// ---------------------------------------------------------------------------
// Kernel 3: fp16 HMMA GEMM, fp32 accumulation.
//   C[m, n] = sum_k g_x[m,k] * g_w[n,k] + bias[n]
//   CTA 256x128, warp tile 64x64 (8 warps), BK=64 (128B rows, SW128),
//   ldmatrix fragments, 3-stage cp.async pipeline, 1 CTA/SM.
//   L2 traffic: (1/BM+1/BN) model -> 4.33 GB (-25% vs 128x128).
// ---------------------------------------------------------------------------
constexpr int BM = 256, BN = 128, BK = 64, NSTAGE = 3;
constexpr int ROWB  = 128;                 // 64 halves = 128 B per row
constexpr int ATILE = BM * ROWB;           // 32768 B
constexpr int BTILE = BN * ROWB;           // 16384 B
constexpr int STAGE = ATILE + BTILE;       // 49152 B
constexpr int SMEM_OFF = 1024;
constexpr int SMEM_TOTAL = SMEM_OFF + NSTAGE * STAGE;   // 148480
constexpr int KCHUNKS = IN_K / BK;         // 64

__global__ void __launch_bounds__(256, 1)
gemm_f16_kernel(const float* __restrict__ bias, float* __restrict__ out) {
    extern __shared__ char smem[];
    uint32_t sb = smem_u32(smem);
    int tid = threadIdx.x, wid = tid >> 5, lid = tid & 31;
    int mBase = blockIdx.x * BM;
    int nBase = blockIdx.y * BN;

    float* biasS = (float*)smem;
    if (tid < BN) biasS[tid] = bias[nBase + tid];

    const char* gA = (const char*)(g_x + (size_t)mBase * IN_K);
    const char* gB = (const char*)(g_w + (size_t)nBase * IN_K);

    // Per stage: A = 256 rows x 8 chunks (8/thread), B = 128 x 8 (4/thread)
    auto load_stage = [&](int chunk, int s) {
        uint32_t base = sb + SMEM_OFF + s * STAGE;
        const char* srcA = gA + chunk * 128;   // 64 halves = 128 B along K
        const char* srcB = gB + chunk * 128;
#pragma unroll
        for (int i = 0; i < 8; i++) {
            int idx = tid + i * 256;
            int r = idx >> 3, j = idx & 7;     // row 0..255, 16B chunk 0..7
            cp_async16(base + swz128(r * 128 + j * 16),
                       srcA + (size_t)r * (IN_K * 2) + j * 16);
        }
        uint32_t bbase = base + ATILE;
#pragma unroll
        for (int i = 0; i < 4; i++) {
            int idx = tid + i * 256;
            int r = idx >> 3, j = idx & 7;     // row 0..127
            cp_async16(bbase + swz128(r * 128 + j * 16),
                       srcB + (size_t)r * (IN_K * 2) + j * 16);
        }
    };

    // Prologue: fill NSTAGE-1 stages
#pragma unroll
    for (int c = 0; c < NSTAGE - 1; c++) { load_stage(c, c); CP_COMMIT(); }

    int wm = (wid & 3) * 64;     // warp m offset (4 m-warps x 64 rows)
    int wn = (wid >> 2) * 64;    // warp n offset (2 n-warps x 64 cols)
    int gid = lid >> 2, tig = lid & 3;

    // ldmatrix lane coords (R13-validated mapping):
    int aRow = lid & 15;
    int aK16 = lid >> 4;
    int bRow = ((lid >> 4) & 1) * 8 + (lid & 7);
    int bK16 = (lid >> 3) & 1;

    float acc[4][8][4];
#pragma unroll
    for (int mi = 0; mi < 4; mi++)
#pragma unroll
        for (int ni = 0; ni < 8; ni++)
#pragma unroll
            for (int j = 0; j < 4; j++) acc[mi][ni][j] = 0.0f;

#pragma unroll 1
    for (int c = 0; c < KCHUNKS; c++) {
        int s = c % NSTAGE;
        CP_WAIT(1);            // oldest pending group (stage s) complete
        __syncthreads();
        if (c + NSTAGE - 1 < KCHUNKS)
            load_stage(c + NSTAGE - 1, (c + NSTAGE - 1) % NSTAGE);
        CP_COMMIT();           // empty group in tail keeps counting consistent

        uint32_t aBase = sb + SMEM_OFF + s * STAGE;
        uint32_t bBase = aBase + ATILE;

#pragma unroll
        for (int ks = 0; ks < 4; ks++) {       // four k16 steps per chunk
            uint32_t a[4][4], b[4][4];
#pragma unroll
            for (int mi = 0; mi < 4; mi++) {
                int m = wm + mi * 16 + aRow;
                ldsm_x4(a[mi], aBase + swz128(m * 128 + ks * 32 + aK16 * 16));
            }
#pragma unroll
            for (int g = 0; g < 4; g++) {
                int n = wn + g * 16 + bRow;
                ldsm_x4(b[g], bBase + swz128(n * 128 + ks * 32 + bK16 * 16));
            }
#pragma unroll
            for (int mi = 0; mi < 4; mi++)
#pragma unroll
                for (int ni = 0; ni < 8; ni++)
                    mma_16816(acc[mi][ni], a[mi], &b[ni >> 1][(ni & 1) * 2]);
        }
    }

    // Epilogue: c0,c1 -> (row gid, cols 2tig,+1); c2,c3 -> row gid+8
#pragma unroll
    for (int mi = 0; mi < 4; mi++) {
        int r0 = mBase + wm + mi * 16 + gid;
#pragma unroll
        for (int ni = 0; ni < 8; ni++) {
            int col = wn + ni * 8 + tig * 2;
            float b0 = biasS[col], b1 = biasS[col + 1];
            float2 v0 = {acc[mi][ni][0] + b0, acc[mi][ni][1] + b1};
            float2 v1 = {acc[mi][ni][2] + b0, acc[mi][ni][3] + b1};
            *(float2*)(out + (size_t)r0 * OUT_N + nBase + col) = v0;
            *(float2*)(out + (size_t)(r0 + 8) * OUT_N + nBase + col) = v1;
        }
    }
}

// ---------------------------------------------------------------------------
// Entry point — identify inputs by element count (robust to metadata order):
//   x: 16777216 (f32), weight_q4: 22544384 (i32),
//   weight_norm: 2818048 (f32), bias: 11008 (f32)
// ---------------------------------------------------------------------------
extern "C" void kernel_launch(void* const* d_in, const int* in_sizes, int n_in,
                              void* d_out, int out_size) {
    const float* x    = (const float*)d_in[0];
    const int*   wq   = (const int*)d_in[1];
    const float* wn   = (const float*)d_in[2];
    const float* bias = (const float*)d_in[3];
    for (int i = 0; i < n_in; i++) {
        switch (in_sizes[i]) {
            case 16777216: x    = (const float*)d_in[i]; break;
            case 22544384: wq   = (const int*)d_in[i];   break;
            case 2818048:  wn   = (const float*)d_in[i]; break;
            case 11008:    bias = (const float*)d_in[i]; break;
            default: break;
        }
    }
    float* out = (float*)d_out;

    dequant_w_kernel<<<(NGRPS + 255) / 256, 256>>>(wq, wn);

    int n4 = (M_ROWS * IN_K) / 4;
    convert_x_kernel<<<(n4 + 255) / 256, 256>>>(x, n4);

    cudaFuncSetAttribute(gemm_f16_kernel,
                         cudaFuncAttributeMaxDynamicSharedMemorySize, SMEM_TOTAL);
    dim3 grid(M_ROWS / BM, OUT_N / BN);   // 16 x 86
    gemm_f16_kernel<<<grid, 256, SMEM_TOTAL>>>(bias, out);
}

// round 16
// speedup vs baseline: 1.1745x; 1.1745x over previous
#include <cuda_runtime.h>
#include <cuda_fp16.h>
#include <cstdint>
#include <cstddef>

// ---------------------------------------------------------------------------
// Problem constants
// ---------------------------------------------------------------------------
#define OUT_N  11008
#define IN_K   4096
#define NGRPS  (OUT_N * IN_K / 16)   // 2818048
#define M_ROWS 4096                  // 2 * 2048

// Scratch (allocation-free rule: __device__ globals)
__device__ __half g_w[(size_t)OUT_N * IN_K];   // dequantized W, [N, K] K-major
__device__ __half g_x[(size_t)M_ROWS * IN_K];  // fp16 x,        [M, K] K-major

// ---------------------------------------------------------------------------
// Helpers (base sm_103 PTX only: cp.async, ldmatrix, mma.sync)
// ---------------------------------------------------------------------------
__device__ __forceinline__ uint32_t smem_u32(const void* p) {
    uint32_t a;
    asm("{ .reg .u64 t; cvta.to.shared.u64 t, %1; cvt.u32.u64 %0, t; }"
        : "=r"(a) : "l"(p));
    return a;
}

__device__ __forceinline__ void cp_async16(uint32_t dst, const void* src) {
    asm volatile("cp.async.cg.shared.global [%0], [%1], 16;"
                 :: "r"(dst), "l"(src) : "memory");
}
#define CP_COMMIT() asm volatile("cp.async.commit_group;" ::: "memory")
#define CP_WAIT(n)  asm volatile("cp.async.wait_group %0;" :: "n"(n) : "memory")

// memory clobber load-bearing: orders the smem read vs wait/barrier
__device__ __forceinline__ void ldsm_x4(uint32_t* r, uint32_t addr) {
    asm volatile("ldmatrix.sync.aligned.m8n8.x4.shared.b16 {%0,%1,%2,%3}, [%4];"
                 : "=r"(r[0]), "=r"(r[1]), "=r"(r[2]), "=r"(r[3])
                 : "r"(addr) : "memory");
}

__device__ __forceinline__ void mma_16816(float* c, const uint32_t* a,
                                          const uint32_t* b) {
    asm volatile(
        "mma.sync.aligned.m16n8k16.row.col.f32.f16.f16.f32 "
        "{%0,%1,%2,%3}, {%4,%5,%6,%7}, {%8,%9}, {%0,%1,%2,%3};"
        : "+f"(c[0]), "+f"(c[1]), "+f"(c[2]), "+f"(c[3])
        : "r"(a[0]), "r"(a[1]), "r"(a[2]), "r"(a[3]), "r"(b[0]), "r"(b[1]));
}

// SW128 swizzle for 128-byte rows (bijective; same map on write & read)
__device__ __forceinline__ uint32_t swz128(uint32_t off) {
    return off ^ ((off >> 3) & 0x70);
}

// ---------------------------------------------------------------------------
// Kernel 1: dequantize packed 4-bit weights -> fp16 [N, K]
//   weight_norm is FLOAT32 (harness upconverts jax f16 -> f32)  [R12-proven]
// ---------------------------------------------------------------------------
__global__ void dequant_w_kernel(const int* __restrict__ q,
                                 const float* __restrict__ norm) {
    int g = blockIdx.x * blockDim.x + threadIdx.x;
    if (g >= NGRPS) return;
    const int4* qp = (const int4*)q + (size_t)g * 2;
    int4 a = qp[0], b = qp[1];
    float n = norm[g];
    float s = n * (2.0f / 15.0f);
    int v[8] = {a.x, a.y, a.z, a.w, b.x, b.y, b.z, b.w};
    __half2 h[8];
#pragma unroll
    for (int j = 0; j < 8; j++) {
        float lo = (float)(v[j] & 15)        * s - n;   // even position 2j
        float hi = (float)((v[j] >> 4) & 15) * s - n;   // odd position 2j+1
        h[j] = __floats2half2_rn(lo, hi);
    }
    uint4* dst = (uint4*)(g_w + (size_t)g * 16);
    dst[0] = *(uint4*)&h[0];
    dst[1] = *(uint4*)&h[4];
}

// ---------------------------------------------------------------------------
// Kernel 2: x fp32 -> fp16
// ---------------------------------------------------------------------------
__global__ void convert_x_kernel(const float* __restrict__ x, int n4) {
    int i = blockIdx.x * blockDim.x + threadIdx.x;
    if (i >= n4) return;
    float4 v = ((const float4*)x)[i];
    __half2* dst = (__half2*)g_x;
    dst[2 * i]     = __floats2half2_rn(v.x, v.y);
    dst[2 * i + 1] = __floats2half2_rn(v.z, v.w);
}

// ---------------------------------------------------------------------------
// Kernel 3: fp16 HMMA GEMM, fp32 accumulation.  [R13 config — best known]
//   C[m, n] = sum_k g_x[m,k] * g_w[n,k] + bias[n]
//   CTA 128x128, warp 32x64, BK=64 (SW128), 3-stage cp.async, 2 CTAs/SM,
//   + explicit fragment double-buffering across the four k16 steps.
// ---------------------------------------------------------------------------
constexpr int BM = 128, BN = 128, BK = 64, NSTAGE = 3;
constexpr int ROWB  = 128;                 // 64 halves = 128 B per row
constexpr int ATILE = BM * ROWB;           // 16384 B
constexpr int STAGE = 2 * ATILE;           // 32768 B (A then B)
constexpr int SMEM_OFF = 1024;
constexpr int SMEM_TOTAL = SMEM_OFF + NSTAGE * STAGE;   // 99328
constexpr int KCHUNKS = IN_K / BK;         // 64

__global__ void __launch_bounds__(256, 2)
gemm_f16_kernel(const float* __restrict__ bias, float* __restrict__ out) {
    extern __shared__ char smem[];
    uint32_t sb = smem_u32(smem);
    int tid = threadIdx.x, wid = tid >> 5, lid = tid & 31;
    int mBase = blockIdx.x * BM;
    int nBase = blockIdx.y * BN;

    float* biasS = (float*)smem;
    if (tid < BN) biasS[tid] = bias[nBase + tid];

    const char* gA = (const char*)(g_x + (size_t)mBase * IN_K);
    const char* gB = (const char*)(g_w + (size_t)nBase * IN_K);

    auto load_stage = [&](int chunk, int s) {
        uint32_t base = sb + SMEM_OFF + s * STAGE;
        const char* srcA = gA + chunk * 128;   // 64 halves = 128 B along K
        const char* srcB = gB + chunk * 128;
#pragma unroll
        for (int i = 0; i < 4; i++) {
            int idx = tid + i * 256;
            int r = idx >> 3, j = idx & 7;     // row 0..127, 16B chunk 0..7
            cp_async16(base + swz128(r * 128 + j * 16),
                       srcA + (size_t)r * (IN_K * 2) + j * 16);
        }
        uint32_t bbase = base + ATILE;
#pragma unroll
        for (int i = 0; i < 4; i++) {
            int idx = tid + i * 256;
            int r = idx >> 3, j = idx & 7;
            cp_async16(bbase + swz128(r * 128 + j * 16),
                       srcB + (size_t)r * (IN_K * 2) + j * 16);
        }
    };

    // Prologue: fill NSTAGE-1 stages
#pragma unroll
    for (int c = 0; c < NSTAGE - 1; c++) { load_stage(c, c); CP_COMMIT(); }

    int wm = (wid & 3) * 32;     // warp m offset (4 rows of warps)
    int wn = (wid >> 2) * 64;    // warp n offset (2 cols of warps)
    int gid = lid >> 2, tig = lid & 3;

    // ldmatrix lane coords (R13-validated mapping):
    int aRow = lid & 15;
    int aK16 = lid >> 4;
    int bRow = ((lid >> 4) & 1) * 8 + (lid & 7);
    int bK16 = (lid >> 3) & 1;

    float acc[2][8][4];
#pragma unroll
    for (int mi = 0; mi < 2; mi++)
#pragma unroll
        for (int ni = 0; ni < 8; ni++)
#pragma unroll
            for (int j = 0; j < 4; j++) acc[mi][ni][j] = 0.0f;

    // Double-buffered fragments across k16 steps
    uint32_t afr[2][2][4], bfr[2][4][4];

#pragma unroll 1
    for (int c = 0; c < KCHUNKS; c++) {
        int s = c % NSTAGE;
        CP_WAIT(1);            // oldest pending group (stage s) complete
        __syncthreads();
        if (c + NSTAGE - 1 < KCHUNKS)
            load_stage(c + NSTAGE - 1, (c + NSTAGE - 1) % NSTAGE);
        CP_COMMIT();           // empty group in tail keeps counting consistent

        uint32_t aBase = sb + SMEM_OFF + s * STAGE;
        uint32_t bBase = aBase + ATILE;

        // Prefetch fragments for ks=0 into buffer 0
#pragma unroll
        for (int mi = 0; mi < 2; mi++) {
            int m = wm + mi * 16 + aRow;
            ldsm_x4(afr[0][mi], aBase + swz128(m * 128 + aK16 * 16));
        }
#pragma unroll
        for (int g = 0; g < 4; g++) {
            int n = wn + g * 16 + bRow;
            ldsm_x4(bfr[0][g], bBase + swz128(n * 128 + bK16 * 16));
        }

#pragma unroll
        for (int ks = 0; ks < 4; ks++) {
            int cur = ks & 1, nxt = cur ^ 1;
            if (ks < 3) {      // prefetch ks+1 while mma issues for ks
#pragma unroll
                for (int mi = 0; mi < 2; mi++) {
                    int m = wm + mi * 16 + aRow;
                    ldsm_x4(afr[nxt][mi],
                            aBase + swz128(m * 128 + (ks + 1) * 32 + aK16 * 16));
                }
#pragma unroll
                for (int g = 0; g < 4; g++) {
                    int n = wn + g * 16 + bRow;
                    ldsm_x4(bfr[nxt][g],
                            bBase + swz128(n * 128 + (ks + 1) * 32 + bK16 * 16));
                }
            }
#pragma unroll
            for (int mi = 0; mi < 2; mi++)
#pragma unroll
                for (int ni = 0; ni < 8; ni++)
                    mma_16816(acc[mi][ni], afr[cur][mi],
                              &bfr[cur][ni >> 1][(ni & 1) * 2]);
        }
    }

    // Epilogue: c0,c1 -> (row gid, cols 2tig,+1); c2,c3 -> row gid+8
#pragma unroll
    for (int mi = 0; mi < 2; mi++) {
        int r0 = mBase + wm + mi * 16 + gid;
#pragma unroll
        for (int ni = 0; ni < 8; ni++) {
            int col = wn + ni * 8 + tig * 2;
            float b0 = biasS[col], b1 = biasS[col + 1];
            float2 v0 = {acc[mi][ni][0] + b0, acc[mi][ni][1] + b1};
            float2 v1 = {acc[mi][ni][2] + b0, acc[mi][ni][3] + b1};
            *(float2*)(out + (size_t)r0 * OUT_N + nBase + col) = v0;
            *(float2*)(out + (size_t)(r0 + 8) * OUT_N + nBase + col) = v1;
        }
    }
}

// ---------------------------------------------------------------------------
// Entry point — identify inputs by element count (robust to metadata order):
//   x: 16777216 (f32), weight_q4: 22544384 (i32),
//   weight_norm: 2818048 (f32), bias: 11008 (f32)
// ---------------------------------------------------------------------------
extern "C" void kernel_launch(void* const* d_in, const int* in_sizes, int n_in,
                              void* d_out, int out_size) {
    const float* x    = (const float*)d_in[0];
    const int*   wq   = (const int*)d_in[1];
    const float* wn   = (const float*)d_in[2];
    const float* bias = (const float*)d_in[3];
    for (int i = 0; i < n_in; i++) {
        switch (in_sizes[i]) {
            case 16777216: x    = (const float*)d_in[i]; break;
            case 22544384: wq   = (const int*)d_in[i];   break;
            case 2818048:  wn   = (const float*)d_in[i]; break;
            case 11008:    bias = (const float*)d_in[i]; break;
            default: break;
        }
    }
    float* out = (float*)d_out;

    dequant_w_kernel<<<(NGRPS + 255) / 256, 256>>>(wq, wn);

    int n4 = (M_ROWS * IN_K) / 4;
    convert_x_kernel<<<(n4 + 255) / 256, 256>>>(x, n4);

    cudaFuncSetAttribute(gemm_f16_kernel,
                         cudaFuncAttributeMaxDynamicSharedMemorySize, SMEM_TOTAL);
    dim3 grid(M_ROWS / BM, OUT_N / BN);   // 32 x 86
    gemm_f16_kernel<<<grid, 256, SMEM_TOTAL>>>(bias, out);
}